// round 6
// baseline (speedup 1.0000x reference)
#include <cuda_runtime.h>
#include <cuda_bf16.h>

#define BB 32
#define HH 4
#define SS 4096
#define MM 128

typedef unsigned long long u64;

__device__ __forceinline__ u64 fma2(u64 a, u64 b, u64 c) {
    u64 d; asm("fma.rn.f32x2 %0,%1,%2,%3;" : "=l"(d) : "l"(a), "l"(b), "l"(c)); return d;
}
__device__ __forceinline__ u64 mul2(u64 a, u64 b) {
    u64 d; asm("mul.rn.f32x2 %0,%1,%2;" : "=l"(d) : "l"(a), "l"(b)); return d;
}
__device__ __forceinline__ u64 pack2(float lo, float hi) {
    u64 r; asm("mov.b64 %0,{%1,%2};" : "=l"(r) : "f"(lo), "f"(hi)); return r;
}
__device__ __forceinline__ float2 unpack2(u64 x) {
    float2 f; asm("mov.b64 {%0,%1},%2;" : "=f"(f.x), "=f"(f.y) : "l"(x)); return f;
}
__device__ __forceinline__ float hadd2(u64 x) {
    const float2 f = unpack2(x); return f.x + f.y;
}

// Scratch: w stored transposed [b][s][h] as float4 per row
__device__ float4 g_w[BB * SS];

// ---------------------------------------------------------------------------
// Kernel 1: 16 lanes per row, 2 rows per warp-step, depth-2 pipeline.
// Stores g_w[b*SS+s] = {dot_h(k_h, mem_s) * rmn_s} (rmn folded in).
// ---------------------------------------------------------------------------
__global__ void __launch_bounds__(256, 3) k1_dots(const float* __restrict__ mem,
                                                  const float* __restrict__ kq) {
    const int b    = blockIdx.x >> 5;        // 32 tiles per b
    const int tile = blockIdx.x & 31;        // 128 rows per tile
    const int warp = threadIdx.x >> 5;
    const int lane = threadIdx.x & 31;
    const int l16  = lane & 15;
    const int rh   = lane >> 4;              // 0/1: which of the pair of rows

    // k in registers: kk[h][0] = cols l16*4.., kk[h][1] = cols 64+l16*4..
    ulonglong2 kk[HH][2];
#pragma unroll
    for (int h = 0; h < HH; ++h) {
        const float* kp = kq + ((b * HH + h) << 7);
        kk[h][0] = *(const ulonglong2*)(kp + l16 * 4);
        kk[h][1] = *(const ulonglong2*)(kp + 64 + l16 * 4);
    }

    // rows: s = tile*128 + warp*16 + rh + 2*step, step = 0..7
    const int s0 = tile * 128 + warp * 16 + rh;
    const float* base = mem + ((size_t)b * SS + s0) * MM;

    ulonglong2 buf[2][2];
    buf[0][0] = *(const ulonglong2*)(base + l16 * 4);
    buf[0][1] = *(const ulonglong2*)(base + 64 + l16 * 4);
    buf[1][0] = *(const ulonglong2*)(base + 2 * MM + l16 * 4);
    buf[1][1] = *(const ulonglong2*)(base + 2 * MM + 64 + l16 * 4);

#pragma unroll
    for (int step = 0; step < 8; ++step) {
        const ulonglong2 v0 = buf[step & 1][0];
        const ulonglong2 v1 = buf[step & 1][1];
        if (step < 6) {
            const float* nb = base + (size_t)(step + 2) * 2 * MM;
            buf[step & 1][0] = *(const ulonglong2*)(nb + l16 * 4);
            buf[step & 1][1] = *(const ulonglong2*)(nb + 64 + l16 * 4);
        }

        u64 ss2 = mul2(v0.x, v0.x);
        ss2 = fma2(v0.y, v0.y, ss2);
        ss2 = fma2(v1.x, v1.x, ss2);
        ss2 = fma2(v1.y, v1.y, ss2);

        u64 d2[HH];
#pragma unroll
        for (int h = 0; h < HH; ++h) {
            u64 t = mul2(v0.x, kk[h][0].x);
            t = fma2(v0.y, kk[h][0].y, t);
            t = fma2(v1.x, kk[h][1].x, t);
            d2[h] = fma2(v1.y, kk[h][1].y, t);
        }

        float ssum = hadd2(ss2);
        float sd[HH];
#pragma unroll
        for (int h = 0; h < HH; ++h) sd[h] = hadd2(d2[h]);

#pragma unroll
        for (int o = 8; o > 0; o >>= 1) {
            ssum += __shfl_xor_sync(0xFFFFFFFFu, ssum, o);
#pragma unroll
            for (int h = 0; h < HH; ++h)
                sd[h] += __shfl_xor_sync(0xFFFFFFFFu, sd[h], o);
        }

        if (l16 == 0) {
            const float rmn = 1.0f / fmaxf(sqrtf(ssum), 1e-8f);
            g_w[b * SS + s0 + 2 * step] = make_float4(sd[0] * rmn, sd[1] * rmn,
                                                      sd[2] * rmn, sd[3] * rmn);
        }
    }
}

// ---------------------------------------------------------------------------
// Kernel 2: per-b block, 512 threads. Softmax over S for all 4 heads (float4).
// Also zero-initializes out[b,:,:].
// ---------------------------------------------------------------------------
__global__ void __launch_bounds__(512) k2_softmax(const float* __restrict__ kq,
                                                  const float* __restrict__ beta,
                                                  float* __restrict__ out) {
    const int b = blockIdx.x;
    const int tid = threadIdx.x;
    const int wid = tid >> 5, lane = tid & 31;

    __shared__ float scl[HH];
    __shared__ float4 red[512];

    if (wid < HH) {
        const float4 kv = ((const float4*)(kq + (b * HH + wid) * MM))[lane];
        float ss = kv.x * kv.x + kv.y * kv.y + kv.z * kv.z + kv.w * kv.w;
#pragma unroll
        for (int o = 16; o > 0; o >>= 1)
            ss += __shfl_xor_sync(0xFFFFFFFFu, ss, o);
        if (lane == 0)
            scl[wid] = beta[b * HH + wid] / fmaxf(sqrtf(ss), 1e-8f);
    }
    if (tid < HH * MM)
        out[b * HH * MM + tid] = 0.0f;
    __syncthreads();

    const float4 sc = make_float4(scl[0], scl[1], scl[2], scl[3]);

    float4 lg[SS / 512];  // 8
    float4 mx = make_float4(-1e30f, -1e30f, -1e30f, -1e30f);
#pragma unroll
    for (int i = 0; i < SS / 512; ++i) {
        float4 v = g_w[b * SS + tid + i * 512];
        v.x *= sc.x; v.y *= sc.y; v.z *= sc.z; v.w *= sc.w;
        lg[i] = v;
        mx.x = fmaxf(mx.x, v.x); mx.y = fmaxf(mx.y, v.y);
        mx.z = fmaxf(mx.z, v.z); mx.w = fmaxf(mx.w, v.w);
    }
    red[tid] = mx; __syncthreads();
    for (int o = 256; o > 0; o >>= 1) {
        if (tid < o) {
            float4 a = red[tid], c = red[tid + o];
            red[tid] = make_float4(fmaxf(a.x, c.x), fmaxf(a.y, c.y),
                                   fmaxf(a.z, c.z), fmaxf(a.w, c.w));
        }
        __syncthreads();
    }
    mx = red[0];
    __syncthreads();

    float4 sum = make_float4(0, 0, 0, 0);
#pragma unroll
    for (int i = 0; i < SS / 512; ++i) {
        float4 v = lg[i];
        v.x = __expf(v.x - mx.x); v.y = __expf(v.y - mx.y);
        v.z = __expf(v.z - mx.z); v.w = __expf(v.w - mx.w);
        lg[i] = v;
        sum.x += v.x; sum.y += v.y; sum.z += v.z; sum.w += v.w;
    }
    red[tid] = sum; __syncthreads();
    for (int o = 256; o > 0; o >>= 1) {
        if (tid < o) {
            float4 a = red[tid], c = red[tid + o];
            red[tid] = make_float4(a.x + c.x, a.y + c.y, a.z + c.z, a.w + c.w);
        }
        __syncthreads();
    }
    const float4 tot = red[0];
    const float4 inv = make_float4(1.0f / tot.x, 1.0f / tot.y,
                                   1.0f / tot.z, 1.0f / tot.w);
#pragma unroll
    for (int i = 0; i < SS / 512; ++i) {
        float4 v = lg[i];
        v.x *= inv.x; v.y *= inv.y; v.z *= inv.z; v.w *= inv.w;
        g_w[b * SS + tid + i * 512] = v;
    }
}

// ---------------------------------------------------------------------------
// Kernel 3: fused write + read, packed f32x2, depth-2 prefetch of (v, w).
// ---------------------------------------------------------------------------
#define NCHUNK 32
#define ROWS_PER_CHUNK (SS / NCHUNK)   // 128
#define K3_ITERS (ROWS_PER_CHUNK / 8)  // 16

__global__ void __launch_bounds__(256, 3) k3_write_read(const float* __restrict__ mem,
                                                        const float* __restrict__ erase,
                                                        const float* __restrict__ add,
                                                        float* __restrict__ out) {
    const int b  = blockIdx.y;
    const int s0 = blockIdx.x * ROWS_PER_CHUNK;
    const int warp = threadIdx.x >> 5;
    const int lane = threadIdx.x & 31;

    __shared__ float acc[HH * MM];
    for (int i = threadIdx.x; i < HH * MM; i += blockDim.x)
        acc[i] = 0.0f;

    u64 ner2[HH][2], ar2[HH][2];
#pragma unroll
    for (int h = 0; h < HH; ++h) {
        const float4 e4 = __ldg((const float4*)(erase + (b * HH + h) * MM) + lane);
        const float4 a4 = __ldg((const float4*)(add   + (b * HH + h) * MM) + lane);
        ner2[h][0] = pack2(-e4.x, -e4.y);
        ner2[h][1] = pack2(-e4.z, -e4.w);
        ar2[h][0]  = pack2(a4.x, a4.y);
        ar2[h][1]  = pack2(a4.z, a4.w);
    }
    const u64 ones = pack2(1.0f, 1.0f);
    __syncthreads();

    u64 racc[HH][2];
#pragma unroll
    for (int h = 0; h < HH; ++h) { racc[h][0] = 0; racc[h][1] = 0; }

    const float4* wbase = &g_w[b * SS + s0 + warp];
    const ulonglong2* vbase =
        (const ulonglong2*)(mem + ((size_t)b * SS + s0 + warp) * MM) + lane;

    ulonglong2 vbuf[2];
    float4 wbuf[2];
    vbuf[0] = vbase[0];            wbuf[0] = __ldg(wbase);
    vbuf[1] = vbase[8 * (MM / 4)]; wbuf[1] = __ldg(wbase + 8);

#pragma unroll
    for (int it = 0; it < K3_ITERS; ++it) {
        const ulonglong2 v = vbuf[it & 1];
        const float4 wq = wbuf[it & 1];
        if (it < K3_ITERS - 2) {
            vbuf[it & 1] = vbase[(size_t)(it + 2) * 8 * (MM / 4)];
            wbuf[it & 1] = __ldg(wbase + (it + 2) * 8);
        }

        u64 w2[HH];
        w2[0] = pack2(wq.x, wq.x); w2[1] = pack2(wq.y, wq.y);
        w2[2] = pack2(wq.z, wq.z); w2[3] = pack2(wq.w, wq.w);

        u64 x0 = v.x, x1 = v.y;
#pragma unroll
        for (int h = 0; h < HH; ++h) {
            const u64 t0  = fma2(ner2[h][0], w2[h], ones);   // 1 - w*e
            const u64 t1  = fma2(ner2[h][1], w2[h], ones);
            const u64 wa0 = mul2(w2[h], ar2[h][0]);          // w*a
            const u64 wa1 = mul2(w2[h], ar2[h][1]);
            x0 = fma2(x0, t0, wa0);
            x1 = fma2(x1, t1, wa1);
        }
#pragma unroll
        for (int h = 0; h < HH; ++h) {
            racc[h][0] = fma2(w2[h], x0, racc[h][0]);
            racc[h][1] = fma2(w2[h], x1, racc[h][1]);
        }
    }

#pragma unroll
    for (int h = 0; h < HH; ++h) {
        const float2 r0 = unpack2(racc[h][0]);
        const float2 r1 = unpack2(racc[h][1]);
        atomicAdd(&acc[h * MM + lane * 4 + 0], r0.x);
        atomicAdd(&acc[h * MM + lane * 4 + 1], r0.y);
        atomicAdd(&acc[h * MM + lane * 4 + 2], r1.x);
        atomicAdd(&acc[h * MM + lane * 4 + 3], r1.y);
    }
    __syncthreads();

    for (int i = threadIdx.x; i < HH * MM; i += blockDim.x)
        atomicAdd(&out[b * HH * MM + i], acc[i]);
}

// ---------------------------------------------------------------------------
extern "C" void kernel_launch(void* const* d_in, const int* in_sizes, int n_in,
                              void* d_out, int out_size) {
    const float* mem   = (const float*)d_in[0];  // (B,S,M)
    const float* kq    = (const float*)d_in[1];  // (B,H,M)
    const float* beta  = (const float*)d_in[2];  // (B,H,1)
    const float* erase = (const float*)d_in[3];  // (B,H,M)
    const float* add   = (const float*)d_in[4];  // (B,H,M)
    float* out = (float*)d_out;                  // (B,H,M)

    (void)in_sizes; (void)n_in; (void)out_size;

    k1_dots<<<BB * 32, 256>>>(mem, kq);
    k2_softmax<<<BB, 512>>>(kq, beta, out);
    k3_write_read<<<dim3(NCHUNK, BB), 256>>>(mem, erase, add, out);
}